// round 10
// baseline (speedup 1.0000x reference)
#include <cuda_runtime.h>
#include <cuda_bf16.h>

// ---------------------------------------------------------------------------
// LorentzLayer: out[b,a] = sum_{c,d} G[c][d][a] * T[b,c,d]
// G_c = Bi_mat @ (W_c * B_c), built in closed form in the kernel prologue.
// Round 10: SOFTWARE PIPELINING. R9 showed DRAM pinned at ~70% across every
// occupancy/layout because each warp's loads are front-batched then followed
// by a ~350-cycle compute/reduce tail with zero loads outstanding (duty ~70%).
// Double-buffered prefetch keeps next unit's 8 LDGs in flight during the
// current unit's FMA+shuffle tail. block=128, 3 blocks/SM (reg cap 170,
// 12 warps/SM, ~40KB loads in flight). G register-resident (R9), grid=444.
// ---------------------------------------------------------------------------

#define NCLUSTER 100
#define BATCH_N  262144
#define NBLOCKS  444            // 148 SMs * 3 resident blocks
#define WPB      4              // warps per block (128 threads)
#define NWARPS   (NBLOCKS * WPB)        // 1776 persistent warps
#define NUNITS   (BATCH_N / 2)  // 131072 two-row units

__device__ __forceinline__ void build_boost(float B[4][4],
                                            float b0, float b1, float b2) {
    float mag2 = b0 * b0 + b1 * b1 + b2 * b2;
    float g = 1.0f / sqrtf(1.0f - mag2);
    float inv_mag2 = 1.0f / mag2;
    float gm1 = g - 1.0f;

    B[0][0] = g;
    B[0][1] = -g * b0; B[0][2] = -g * b1; B[0][3] = -g * b2;
    B[1][0] = -g * b0; B[2][0] = -g * b1; B[3][0] = -g * b2;

    float bb[3] = {b0, b1, b2};
    #pragma unroll
    for (int i = 0; i < 3; i++) {
        #pragma unroll
        for (int j = 0; j < 3; j++) {
            float v = gm1 * bb[i] * bb[j] * inv_mag2;
            if (i == j) v += 1.0f;
            B[i + 1][j + 1] = v;
        }
    }
}

// Gd[d].{x,y,z,w} = (Bim @ (w * Bc))[a=0..3][d]   (column d, components = a)
__device__ __forceinline__ void make_G(const float Bim[4][4],
                                       const float* __restrict__ Bo,
                                       float w, int c, float4 Gd[4]) {
    float Bc[4][4];
    build_boost(Bc, Bo[3 * c + 0], Bo[3 * c + 1], Bo[3 * c + 2]);
    #pragma unroll
    for (int d = 0; d < 4; d++) {
        float s0 = 0.f, s1 = 0.f, s2 = 0.f, s3 = 0.f;
        #pragma unroll
        for (int m = 0; m < 4; m++) {
            s0 += Bim[0][m] * Bc[m][d];
            s1 += Bim[1][m] * Bc[m][d];
            s2 += Bim[2][m] * Bc[m][d];
            s3 += Bim[3][m] * Bc[m][d];
        }
        Gd[d] = make_float4(s0 * w, s1 * w, s2 * w, s3 * w);
    }
}

#define ACCUM4(v0, v1, G)                                               \
    do {                                                                \
        ax0 += v0.x * G[0].x + v0.y * G[1].x + v0.z * G[2].x + v0.w * G[3].x; \
        ay0 += v0.x * G[0].y + v0.y * G[1].y + v0.z * G[2].y + v0.w * G[3].y; \
        az0 += v0.x * G[0].z + v0.y * G[1].z + v0.z * G[2].z + v0.w * G[3].z; \
        aw0 += v0.x * G[0].w + v0.y * G[1].w + v0.z * G[2].w + v0.w * G[3].w; \
        ax1 += v1.x * G[0].x + v1.y * G[1].x + v1.z * G[2].x + v1.w * G[3].x; \
        ay1 += v1.x * G[0].y + v1.y * G[1].y + v1.z * G[2].y + v1.w * G[3].y; \
        az1 += v1.x * G[0].z + v1.y * G[1].z + v1.z * G[2].z + v1.w * G[3].z; \
        aw1 += v1.x * G[0].w + v1.y * G[1].w + v1.z * G[2].w + v1.w * G[3].w; \
    } while (0)

// Component-folding butterfly: every lane ends with the full-warp sum of
// component (lane&3). 9 shuffles per 4-vector. (Verified R8/R9.)
__device__ __forceinline__ float reduce_vec4(float ax, float ay, float az,
                                             float aw, int lane) {
    const unsigned F = 0xffffffffu;
    float sx = ax + __shfl_xor_sync(F, ax, 1);
    float sy = ay + __shfl_xor_sync(F, ay, 1);
    float sz = az + __shfl_xor_sync(F, az, 1);
    float sw = aw + __shfl_xor_sync(F, aw, 1);
    float p = (lane & 1) ? sy : sx;
    float q = (lane & 1) ? sw : sz;
    p += __shfl_xor_sync(F, p, 2);
    q += __shfl_xor_sync(F, q, 2);
    float r = (lane & 2) ? q : p;
    r += __shfl_xor_sync(F, r, 4);
    r += __shfl_xor_sync(F, r, 8);
    r += __shfl_xor_sync(F, r, 16);
    return r;   // lane l holds component (l&3)
}

// Issue the 6 main (+2 tail) loads for unit u into the named registers.
#define LOADV(v0, v1, v2, v3, v4, v5, vt0, vt1, u)                      \
    do {                                                                \
        const float4* _t0 = (const float4*)T + (size_t)(u) * 200;       \
        const float4* _t1 = _t0 + 100;                                  \
        v0 = __ldcs(_t0 + lane);                                        \
        v1 = __ldcs(_t0 + 32 + lane);                                   \
        v2 = __ldcs(_t0 + 64 + lane);                                   \
        v3 = __ldcs(_t1 + lane);                                        \
        v4 = __ldcs(_t1 + 32 + lane);                                   \
        v5 = __ldcs(_t1 + 64 + lane);                                   \
        if (lane < 4) {                                                 \
            vt0 = __ldcs(_t0 + 96 + lane);                              \
            vt1 = __ldcs(_t1 + 96 + lane);                              \
        }                                                               \
    } while (0)

// Consume one unit's registers: FMA, butterfly reduce, store.
#define PROCESS(v0, v1, v2, v3, v4, v5, vt0, vt1, u)                    \
    do {                                                                \
        float ax0 = 0.f, ay0 = 0.f, az0 = 0.f, aw0 = 0.f;               \
        float ax1 = 0.f, ay1 = 0.f, az1 = 0.f, aw1 = 0.f;               \
        ACCUM4(v0, v3, G0);                                             \
        ACCUM4(v1, v4, G1);                                             \
        ACCUM4(v2, v5, G2);                                             \
        ACCUM4(vt0, vt1, GT);                                           \
        float r0 = reduce_vec4(ax0, ay0, az0, aw0, lane);               \
        float r1 = reduce_vec4(ax1, ay1, az1, aw1, lane);               \
        if (lane < 4) {                                                 \
            out[(size_t)(u) * 8 + lane]     = r0;                       \
            out[(size_t)(u) * 8 + 4 + lane] = r1;                       \
        }                                                               \
    } while (0)

__global__ __launch_bounds__(128, 3)
void lorentz_main_kernel(const float* __restrict__ T,
                         const float* __restrict__ Bo,
                         const float* __restrict__ Bi,
                         const float* __restrict__ W,
                         float* __restrict__ out) {
    __shared__ float4 gtail[4][4];   // G for clusters 96..99, [c-96][d]

    int tid  = threadIdx.x;
    int lane = tid & 31;
    int warp = tid >> 5;

    // --- prologue: register-resident G (once per persistent block) ---
    float Bim[4][4];
    build_boost(Bim, Bi[0], Bi[1], Bi[2]);

    float4 G0[4], G1[4], G2[4], GT[4];
    make_G(Bim, Bo, W[lane],      lane,      G0);
    make_G(Bim, Bo, W[32 + lane], 32 + lane, G1);
    make_G(Bim, Bo, W[64 + lane], 64 + lane, G2);

    if (tid < 4) {
        float4 gt[4];
        make_G(Bim, Bo, W[96 + tid], 96 + tid, gt);
        gtail[tid][0] = gt[0];
        gtail[tid][1] = gt[1];
        gtail[tid][2] = gt[2];
        gtail[tid][3] = gt[3];
    }
    __syncthreads();
    GT[0] = gtail[lane & 3][0];
    GT[1] = gtail[lane & 3][1];
    GT[2] = gtail[lane & 3][2];
    GT[3] = gtail[lane & 3][3];

    const float4 ZERO = make_float4(0.f, 0.f, 0.f, 0.f);
    int wid = blockIdx.x * WPB + warp;

    // Double-buffered registers. Tail regs on lanes >=4 stay ZERO forever.
    float4 A0, A1, A2, A3, A4, A5, AT0 = ZERO, AT1 = ZERO;
    float4 B0, B1, B2, B3, B4, B5, BT0 = ZERO, BT1 = ZERO;

    int cur = wid;                       // wid < NWARPS <= NUNITS always
    LOADV(A0, A1, A2, A3, A4, A5, AT0, AT1, cur);

    // Ping-pong pipeline: prefetch other buffer, then consume current.
    while (true) {
        int nxt = cur + NWARPS;
        if (nxt < NUNITS) LOADV(B0, B1, B2, B3, B4, B5, BT0, BT1, nxt);
        PROCESS(A0, A1, A2, A3, A4, A5, AT0, AT1, cur);
        cur = nxt;
        if (cur >= NUNITS) break;

        nxt = cur + NWARPS;
        if (nxt < NUNITS) LOADV(A0, A1, A2, A3, A4, A5, AT0, AT1, nxt);
        PROCESS(B0, B1, B2, B3, B4, B5, BT0, BT1, cur);
        cur = nxt;
        if (cur >= NUNITS) break;
    }
}

extern "C" void kernel_launch(void* const* d_in, const int* in_sizes, int n_in,
                              void* d_out, int out_size) {
    const float* T  = (const float*)d_in[0];   // (262144, 100, 4)
    const float* Bo = (const float*)d_in[1];   // (100, 3)
    const float* Bi = (const float*)d_in[2];   // (1, 3)
    const float* W  = (const float*)d_in[3];   // (100, 1)
    // d_in[4] = K_mats — encoded analytically in build_boost.

    float* out = (float*)d_out;                // (262144, 1, 4)

    lorentz_main_kernel<<<NBLOCKS, 128>>>(T, Bo, Bi, W, out);
}

// round 11
// speedup vs baseline: 1.0997x; 1.0997x over previous
#include <cuda_runtime.h>
#include <cuda_bf16.h>
#include <cstdint>

// ---------------------------------------------------------------------------
// LorentzLayer: out[b,a] = sum_{c,d} G[c][d][a] * T[b,c,d]
// Round 11: TMA-BULK STREAMING. Five LDG-path variants all pinned at
// 5.5-5.9 TB/s regardless of occupancy/layout/prefetch -> per-SM L1tex
// outstanding-sector cap. Switch HBM->SMEM to cp.async.bulk (TMA engine
// queue, bypasses L1 MSHRs): 148 persistent blocks x 512 threads, 3-stage
// ring of 32-row (51.2KB) tiles with mbarrier full/empty pipeline, 16 warps
// compute 2 rows each from SMEM (register-resident G, butterfly reduce).
// ---------------------------------------------------------------------------

#define NCLUSTER   100
#define BATCH_N    262144
#define NBLOCKS    148
#define THREADS    512
#define NWARP      16
#define TILE_ROWS  32
#define ROW_BYTES  1600                       // 400 floats
#define TILE_BYTES (TILE_ROWS * ROW_BYTES)    // 51200
#define NTILES     (BATCH_N / TILE_ROWS)      // 8192
#define STAGES     3

// ---------------- mbarrier / bulk-copy primitives ----------------

__device__ __forceinline__ uint32_t s2u(const void* p) {
    return (uint32_t)__cvta_generic_to_shared(p);
}
__device__ __forceinline__ void mbar_init(uint32_t a, uint32_t cnt) {
    asm volatile("mbarrier.init.shared.b64 [%0], %1;" :: "r"(a), "r"(cnt) : "memory");
}
__device__ __forceinline__ void mbar_expect_tx(uint32_t a, uint32_t bytes) {
    asm volatile("mbarrier.arrive.expect_tx.shared.b64 _, [%0], %1;"
                 :: "r"(a), "r"(bytes) : "memory");
}
__device__ __forceinline__ void mbar_arrive(uint32_t a) {
    asm volatile("mbarrier.arrive.shared.b64 _, [%0];" :: "r"(a) : "memory");
}
__device__ __forceinline__ void mbar_wait(uint32_t a, uint32_t ph) {
    asm volatile(
        "{\n\t.reg .pred p;\n"
        "WL%=:\n\t"
        "mbarrier.try_wait.parity.shared.b64 p, [%0], %1;\n\t"
        "@!p bra WL%=;\n\t}"
        :: "r"(a), "r"(ph) : "memory");
}
__device__ __forceinline__ void bulk_g2s(uint32_t dst, const void* src,
                                         uint32_t bytes, uint32_t mbar) {
    asm volatile(
        "cp.async.bulk.shared::cta.global.mbarrier::complete_tx::bytes "
        "[%0], [%1], %2, [%3];"
        :: "r"(dst), "l"((uint64_t)__cvta_generic_to_global(src)),
           "r"(bytes), "r"(mbar) : "memory");
}

// ---------------- closed-form G construction ----------------

__device__ __forceinline__ void build_boost(float B[4][4],
                                            float b0, float b1, float b2) {
    float mag2 = b0 * b0 + b1 * b1 + b2 * b2;
    float g = 1.0f / sqrtf(1.0f - mag2);
    float inv_mag2 = 1.0f / mag2;
    float gm1 = g - 1.0f;

    B[0][0] = g;
    B[0][1] = -g * b0; B[0][2] = -g * b1; B[0][3] = -g * b2;
    B[1][0] = -g * b0; B[2][0] = -g * b1; B[3][0] = -g * b2;

    float bb[3] = {b0, b1, b2};
    #pragma unroll
    for (int i = 0; i < 3; i++) {
        #pragma unroll
        for (int j = 0; j < 3; j++) {
            float v = gm1 * bb[i] * bb[j] * inv_mag2;
            if (i == j) v += 1.0f;
            B[i + 1][j + 1] = v;
        }
    }
}

// Gd[d].{x,y,z,w} = (Bim @ (w * Bc))[a=0..3][d]
__device__ __forceinline__ void make_G(const float Bim[4][4],
                                       const float* __restrict__ Bo,
                                       float w, int c, float4 Gd[4]) {
    float Bc[4][4];
    build_boost(Bc, Bo[3 * c + 0], Bo[3 * c + 1], Bo[3 * c + 2]);
    #pragma unroll
    for (int d = 0; d < 4; d++) {
        float s0 = 0.f, s1 = 0.f, s2 = 0.f, s3 = 0.f;
        #pragma unroll
        for (int m = 0; m < 4; m++) {
            s0 += Bim[0][m] * Bc[m][d];
            s1 += Bim[1][m] * Bc[m][d];
            s2 += Bim[2][m] * Bc[m][d];
            s3 += Bim[3][m] * Bc[m][d];
        }
        Gd[d] = make_float4(s0 * w, s1 * w, s2 * w, s3 * w);
    }
}

#define ACCUM4(v0, v1, G)                                               \
    do {                                                                \
        ax0 += v0.x * G[0].x + v0.y * G[1].x + v0.z * G[2].x + v0.w * G[3].x; \
        ay0 += v0.x * G[0].y + v0.y * G[1].y + v0.z * G[2].y + v0.w * G[3].y; \
        az0 += v0.x * G[0].z + v0.y * G[1].z + v0.z * G[2].z + v0.w * G[3].z; \
        aw0 += v0.x * G[0].w + v0.y * G[1].w + v0.z * G[2].w + v0.w * G[3].w; \
        ax1 += v1.x * G[0].x + v1.y * G[1].x + v1.z * G[2].x + v1.w * G[3].x; \
        ay1 += v1.x * G[0].y + v1.y * G[1].y + v1.z * G[2].y + v1.w * G[3].y; \
        az1 += v1.x * G[0].z + v1.y * G[1].z + v1.z * G[2].z + v1.w * G[3].z; \
        aw1 += v1.x * G[0].w + v1.y * G[1].w + v1.z * G[2].w + v1.w * G[3].w; \
    } while (0)

// Component-folding butterfly (verified R8-R10): every lane ends with the
// full-warp sum of component (lane&3). 9 shuffles per 4-vector.
__device__ __forceinline__ float reduce_vec4(float ax, float ay, float az,
                                             float aw, int lane) {
    const unsigned F = 0xffffffffu;
    float sx = ax + __shfl_xor_sync(F, ax, 1);
    float sy = ay + __shfl_xor_sync(F, ay, 1);
    float sz = az + __shfl_xor_sync(F, az, 1);
    float sw = aw + __shfl_xor_sync(F, aw, 1);
    float p = (lane & 1) ? sy : sx;
    float q = (lane & 1) ? sw : sz;
    p += __shfl_xor_sync(F, p, 2);
    q += __shfl_xor_sync(F, q, 2);
    float r = (lane & 2) ? q : p;
    r += __shfl_xor_sync(F, r, 4);
    r += __shfl_xor_sync(F, r, 8);
    r += __shfl_xor_sync(F, r, 16);
    return r;   // lane l holds component (l&3)
}

// ---------------- main kernel ----------------

__global__ __launch_bounds__(THREADS, 1)
void lorentz_main_kernel(const float* __restrict__ T,
                         const float* __restrict__ Bo,
                         const float* __restrict__ Bi,
                         const float* __restrict__ W,
                         float* __restrict__ out) {
    extern __shared__ __align__(128) char dsm[];   // STAGES * TILE_BYTES
    __shared__ float4 gtail[4][4];
    __shared__ __align__(8) uint64_t mbars[2 * STAGES];  // full[0..2], empty[3..5]

    int tid  = threadIdx.x;
    int lane = tid & 31;
    int warp = tid >> 5;
    int bid  = blockIdx.x;

    // --- register-resident G prologue (R9 design) ---
    float Bim[4][4];
    build_boost(Bim, Bi[0], Bi[1], Bi[2]);

    float4 G0[4], G1[4], G2[4], GT[4];
    make_G(Bim, Bo, W[lane],      lane,      G0);
    make_G(Bim, Bo, W[32 + lane], 32 + lane, G1);
    make_G(Bim, Bo, W[64 + lane], 64 + lane, G2);

    if (tid < 4) {
        float4 gt[4];
        make_G(Bim, Bo, W[96 + tid], 96 + tid, gt);
        gtail[tid][0] = gt[0];
        gtail[tid][1] = gt[1];
        gtail[tid][2] = gt[2];
        gtail[tid][3] = gt[3];
    }

    if (tid == 0) {
        #pragma unroll
        for (int s = 0; s < STAGES; s++) {
            mbar_init(s2u(&mbars[s]), 1);               // full: 1 producer arrive
            mbar_init(s2u(&mbars[STAGES + s]), NWARP);  // empty: 16 warp arrives
        }
    }
    __syncthreads();

    GT[0] = gtail[lane & 3][0];
    GT[1] = gtail[lane & 3][1];
    GT[2] = gtail[lane & 3][2];
    GT[3] = gtail[lane & 3][3];

    // tiles for this block: bid, bid+148, ... (contiguous 32-row chunks)
    int mytiles = (NTILES - bid + NBLOCKS - 1) / NBLOCKS;

    // --- producer prologue: fill up to STAGES stages ---
    if (tid == 0) {
        int npro = mytiles < STAGES ? mytiles : STAGES;
        for (int p = 0; p < npro; p++) {
            uint32_t fb = s2u(&mbars[p]);
            mbar_expect_tx(fb, TILE_BYTES);
            bulk_g2s(s2u(dsm) + p * TILE_BYTES,
                     T + (size_t)(bid + p * NBLOCKS) * TILE_ROWS * 400,
                     TILE_BYTES, fb);
        }
    }

    const float4 ZERO = make_float4(0.f, 0.f, 0.f, 0.f);

    for (int k = 0; k < mytiles; k++) {
        int s = k % STAGES;
        uint32_t ph = (uint32_t)((k / STAGES) & 1);
        uint32_t fb = s2u(&mbars[s]);
        uint32_t eb = s2u(&mbars[STAGES + s]);

        mbar_wait(fb, ph);   // tile k resident in stage s

        const char* SB = dsm + s * TILE_BYTES;
        const float4* t0 = (const float4*)(SB + warp * 2 * ROW_BYTES);
        const float4* t1 = t0 + 100;

        float4 v00 = t0[lane];
        float4 v01 = t0[32 + lane];
        float4 v02 = t0[64 + lane];
        float4 v10 = t1[lane];
        float4 v11 = t1[32 + lane];
        float4 v12 = t1[64 + lane];
        float4 vt0 = ZERO, vt1 = ZERO;
        if (lane < 4) {
            vt0 = t0[96 + lane];
            vt1 = t1[96 + lane];
        }

        float ax0 = 0.f, ay0 = 0.f, az0 = 0.f, aw0 = 0.f;
        float ax1 = 0.f, ay1 = 0.f, az1 = 0.f, aw1 = 0.f;
        ACCUM4(v00, v10, G0);
        ACCUM4(v01, v11, G1);
        ACCUM4(v02, v12, G2);
        ACCUM4(vt0, vt1, GT);

        float r0 = reduce_vec4(ax0, ay0, az0, aw0, lane);
        float r1 = reduce_vec4(ax1, ay1, az1, aw1, lane);

        int grow = (bid + k * NBLOCKS) * TILE_ROWS + warp * 2;
        if (lane < 4) {
            out[(size_t)grow * 4 + lane]     = r0;
            out[(size_t)grow * 4 + 4 + lane] = r1;
        }

        __syncwarp();
        if (lane == 0) mbar_arrive(eb);   // this warp done with stage s

        // producer: refill stage s with tile k+STAGES once all warps drained it
        if (tid == 0 && k + STAGES < mytiles) {
            mbar_wait(eb, ph);
            mbar_expect_tx(fb, TILE_BYTES);
            bulk_g2s(s2u(dsm) + s * TILE_BYTES,
                     T + (size_t)(bid + (k + STAGES) * NBLOCKS) * TILE_ROWS * 400,
                     TILE_BYTES, fb);
        }
    }
}

extern "C" void kernel_launch(void* const* d_in, const int* in_sizes, int n_in,
                              void* d_out, int out_size) {
    const float* T  = (const float*)d_in[0];   // (262144, 100, 4)
    const float* Bo = (const float*)d_in[1];   // (100, 3)
    const float* Bi = (const float*)d_in[2];   // (1, 3)
    const float* W  = (const float*)d_in[3];   // (100, 1)
    // d_in[4] = K_mats — encoded analytically in build_boost.

    float* out = (float*)d_out;                // (262144, 1, 4)

    static bool attr_set = false;
    if (!attr_set) {   // idempotent attribute config (not a graph/stream op)
        cudaFuncSetAttribute(lorentz_main_kernel,
                             cudaFuncAttributeMaxDynamicSharedMemorySize,
                             STAGES * TILE_BYTES);
        attr_set = true;
    }

    lorentz_main_kernel<<<NBLOCKS, THREADS, STAGES * TILE_BYTES>>>(
        T, Bo, Bi, W, out);
}